// round 7
// baseline (speedup 1.0000x reference)
#include <cuda_runtime.h>

// KPN 5x5 per-pixel convolution — barrier-free, 8 pixels/thread (1KB warp bursts).
// frames: (B=16, N=1, C=3, H=256, W=256) float32   (L2-resident, reused via L1/L2)
// core:   (B=16, N=1, 25,  C=3, H=256, W=256) float32 (streamed once, evict-first)
// out:    (B=16, C=3, H=256, W=256) float32
//
// pred[b,c,h,w] = sum_{i,j} core[b,0,i*5+j,c,h,w] * frame_pad[b,0,c,h+i,w+j]
// zero padding 2 each side (rate=1).

#define KK 5
#define PAD 2
#define WID 256
#define HEI 256
#define CH 3
#define TILE_H 4
#define TX 32                       // threads in x; each covers 8 pixels -> warp = 1KB row

__global__ __launch_bounds__(TX * TILE_H, 10)
void kpn_conv_kernel(const float* __restrict__ frames,
                     const float* __restrict__ core,
                     float* __restrict__ out) {
    const int tile = blockIdx.x;    // H / TILE_H
    const int c    = blockIdx.y;    // channel
    const int b    = blockIdx.z;    // batch

    const size_t plane   = (size_t)HEI * WID;                 // 65536
    const float* fbase   = frames + ((size_t)b * CH + c) * plane;
    const float* cbase   = core   + ((size_t)b * 25 * CH + c) * plane;
    const size_t cstride = (size_t)CH * plane;                // tap stride

    const int w8 = threadIdx.x * 8;                           // first pixel col
    const int h  = tile * TILE_H + threadIdx.y;               // output row

    const float* crow = cbase + (size_t)h * WID + w8;

    const float4 f4z = make_float4(0.f, 0.f, 0.f, 0.f);
    float4 accA = f4z;   // pixels w8 .. w8+3
    float4 accB = f4z;   // pixels w8+4 .. w8+7

    // i-loop NOT unrolled: front-batched LDG run stays ~14 (4 frame + 10 core),
    // below the cross-CTA L1tex-queue contention regime. No smem, no barriers.
#pragma unroll 1
    for (int i = 0; i < KK; i++) {
        const int gh = h - PAD + i;
        const bool vh = ((unsigned)gh < (unsigned)HEI);
        const float* frow = fbase + (size_t)gh * WID + w8;

        // 16-float window: cols w8-4 .. w8+11 (aligned LDG.128, edge-predicated)
        const float4 fa = (vh && w8 != 0)
                              ? __ldg(reinterpret_cast<const float4*>(frow - 4)) : f4z;
        const float4 fb = vh ? __ldg(reinterpret_cast<const float4*>(frow))      : f4z;
        const float4 fc = vh ? __ldg(reinterpret_cast<const float4*>(frow + 4))  : f4z;
        const float4 fd = (vh && w8 != WID - 8)
                              ? __ldg(reinterpret_cast<const float4*>(frow + 8)) : f4z;
        const float s[16] = {fa.x, fa.y, fa.z, fa.w,
                             fb.x, fb.y, fb.z, fb.w,
                             fc.x, fc.y, fc.z, fc.w,
                             fd.x, fd.y, fd.z, fd.w};

        const float* ci = crow + (size_t)(i * KK) * cstride;
#pragma unroll
        for (int j = 0; j < KK; j++) {
            // core read exactly once — streaming, evict-first; warp-wide this is
            // a 1KB contiguous burst per tap.
            const float* ct = ci + (size_t)j * cstride;
            const float4 cvA = __ldcs(reinterpret_cast<const float4*>(ct));
            const float4 cvB = __ldcs(reinterpret_cast<const float4*>(ct + 4));
            // pixel p (col w8+p), tap j -> frame col w8+p+j-2 = s[p+j+2]
            accA.x = fmaf(cvA.x, s[j + 2], accA.x);
            accA.y = fmaf(cvA.y, s[j + 3], accA.y);
            accA.z = fmaf(cvA.z, s[j + 4], accA.z);
            accA.w = fmaf(cvA.w, s[j + 5], accA.w);
            accB.x = fmaf(cvB.x, s[j + 6], accB.x);
            accB.y = fmaf(cvB.y, s[j + 7], accB.y);
            accB.z = fmaf(cvB.z, s[j + 8], accB.z);
            accB.w = fmaf(cvB.w, s[j + 9], accB.w);
        }
    }

    float* orow = out + ((size_t)b * CH + c) * plane + (size_t)h * WID + w8;
    __stcs(reinterpret_cast<float4*>(orow), accA);
    __stcs(reinterpret_cast<float4*>(orow + 4), accB);
}

extern "C" void kernel_launch(void* const* d_in, const int* in_sizes, int n_in,
                              void* d_out, int out_size) {
    const float* frames = (const float*)d_in[0];
    const float* core   = (const float*)d_in[1];
    // d_in[2] = rate (scalar, fixed 1 for this instance)
    float* out = (float*)d_out;

    dim3 block(TX, TILE_H, 1);              // 128 threads
    dim3 grid(HEI / TILE_H, CH, 16);        // 64 x 3 x 16 = 3072 CTAs
    kpn_conv_kernel<<<grid, block>>>(frames, core, out);
}

// round 8
// speedup vs baseline: 1.0127x; 1.0127x over previous
#include <cuda_runtime.h>

// KPN 5x5 per-pixel convolution — barrier-free, smem-free, 2 rows x 4 cols per thread.
// frames: (B=16, N=1, C=3, H=256, W=256) float32   (L1/L2-resident reuse)
// core:   (B=16, N=1, 25,  C=3, H=256, W=256) float32 (streamed once, evict-first)
// out:    (B=16, C=3, H=256, W=256) float32
//
// pred[b,c,h,w] = sum_{i,j} core[b,0,i*5+j,c,h,w] * frame_pad[b,0,c,h+i,w+j]
// zero padding 2 each side (rate=1).

#define KK 5
#define PAD 2
#define WID 256
#define HEI 256
#define CH 3
#define TILE_H 8                     // rows per CTA (4 thread-rows x 2 rows/thread)
#define TX 64                        // threads in x; each covers 4 pixels

__global__ __launch_bounds__(TX * 4, 6)
void kpn_conv_kernel(const float* __restrict__ frames,
                     const float* __restrict__ core,
                     float* __restrict__ out) {
    const int tile = blockIdx.x;    // H / TILE_H
    const int c    = blockIdx.y;    // channel
    const int b    = blockIdx.z;    // batch

    const size_t plane   = (size_t)HEI * WID;                 // 65536
    const float* fbase   = frames + ((size_t)b * CH + c) * plane;
    const float* cbase   = core   + ((size_t)b * 25 * CH + c) * plane;
    const size_t cstride = (size_t)CH * plane;                // tap stride

    const int w4 = threadIdx.x * 4;                           // first pixel col
    const int h  = tile * TILE_H + threadIdx.y * 2;           // first of 2 rows

    const float* crow = cbase + (size_t)h * WID + w4;

    const float4 f4z = make_float4(0.f, 0.f, 0.f, 0.f);
    float4 acc0 = f4z;   // row h
    float4 acc1 = f4z;   // row h+1

    // Rolled i-loop over the 6 frame rows the two outputs need (h-2 .. h+3).
    // Row r contributes to row h as tap i0 = r-(h-2) when 0<=i0<5,
    // and to row h+1 as tap i1 = i0-1 when 0<=i1<5.
#pragma unroll 1
    for (int r = 0; r < KK + 1; r++) {
        const int gh = h - PAD + r;
        const bool vh = ((unsigned)gh < (unsigned)HEI);
        const float* frow = fbase + (size_t)gh * WID + w4;

        // 12-float window: cols w4-4 .. w4+7 (aligned LDG.128, edge-predicated)
        const float4 fa = (vh && w4 != 0)
                              ? __ldg(reinterpret_cast<const float4*>(frow - 4)) : f4z;
        const float4 fb = vh ? __ldg(reinterpret_cast<const float4*>(frow))      : f4z;
        const float4 fc = (vh && w4 != WID - 4)
                              ? __ldg(reinterpret_cast<const float4*>(frow + 4)) : f4z;
        const float s[12] = {fa.x, fa.y, fa.z, fa.w,
                             fb.x, fb.y, fb.z, fb.w,
                             fc.x, fc.y, fc.z, fc.w};

        // Row h, tap i0 = r (valid for r in 0..4)
        if (r < KK) {
            const float* ci = crow + (size_t)(r * KK) * cstride;
#pragma unroll
            for (int j = 0; j < KK; j++) {
                const float4 cv =
                    __ldcs(reinterpret_cast<const float4*>(ci + (size_t)j * cstride));
                acc0.x = fmaf(cv.x, s[j + 2], acc0.x);
                acc0.y = fmaf(cv.y, s[j + 3], acc0.y);
                acc0.z = fmaf(cv.z, s[j + 4], acc0.z);
                acc0.w = fmaf(cv.w, s[j + 5], acc0.w);
            }
        }

        // Row h+1, tap i1 = r-1 (valid for r in 1..5)
        if (r >= 1) {
            const float* ci = crow + (size_t)WID
                            + (size_t)((r - 1) * KK) * cstride;
#pragma unroll
            for (int j = 0; j < KK; j++) {
                const float4 cv =
                    __ldcs(reinterpret_cast<const float4*>(ci + (size_t)j * cstride));
                acc1.x = fmaf(cv.x, s[j + 2], acc1.x);
                acc1.y = fmaf(cv.y, s[j + 3], acc1.y);
                acc1.z = fmaf(cv.z, s[j + 4], acc1.z);
                acc1.w = fmaf(cv.w, s[j + 5], acc1.w);
            }
        }
    }

    float* orow = out + ((size_t)b * CH + c) * plane + (size_t)h * WID + w4;
    __stcs(reinterpret_cast<float4*>(orow), acc0);
    __stcs(reinterpret_cast<float4*>(orow + WID), acc1);
}

extern "C" void kernel_launch(void* const* d_in, const int* in_sizes, int n_in,
                              void* d_out, int out_size) {
    const float* frames = (const float*)d_in[0];
    const float* core   = (const float*)d_in[1];
    // d_in[2] = rate (scalar, fixed 1 for this instance)
    float* out = (float*)d_out;

    dim3 block(TX, 4, 1);                   // 256 threads, 8 output rows per CTA
    dim3 grid(HEI / TILE_H, CH, 16);        // 32 x 3 x 16 = 1536 CTAs
    kpn_conv_kernel<<<grid, block>>>(frames, core, out);
}

// round 9
// speedup vs baseline: 1.0429x; 1.0298x over previous
#include <cuda_runtime.h>

// KPN 5x5 per-pixel convolution — barrier-free, smem-free, 2 rows x 4 cols/thread,
// peeled row edges, 128-thread CTAs for fine tail packing.
// frames: (B=16, N=1, C=3, H=256, W=256) float32   (L1/L2-resident reuse)
// core:   (B=16, N=1, 25,  C=3, H=256, W=256) float32 (streamed once, evict-first)
// out:    (B=16, C=3, H=256, W=256) float32
//
// pred[b,c,h,w] = sum_{i,j} core[b,0,i*5+j,c,h,w] * frame_pad[b,0,c,h+i,w+j]
// zero padding 2 each side (rate=1).

#define KK 5
#define PAD 2
#define WID 256
#define HEI 256
#define CH 3
#define TILE_H 4                     // rows per CTA (2 thread-rows x 2 rows/thread)
#define TX 64                        // threads in x; each covers 4 pixels

__device__ __forceinline__ void frame_window(const float* __restrict__ fbase,
                                             int gh, int w4, float s[12]) {
    const float4 f4z = make_float4(0.f, 0.f, 0.f, 0.f);
    const bool vh = ((unsigned)gh < (unsigned)HEI);
    const float* frow = fbase + (size_t)gh * WID + w4;
    const float4 fa = (vh && w4 != 0)
                          ? __ldg(reinterpret_cast<const float4*>(frow - 4)) : f4z;
    const float4 fb = vh ? __ldg(reinterpret_cast<const float4*>(frow))      : f4z;
    const float4 fc = (vh && w4 != WID - 4)
                          ? __ldg(reinterpret_cast<const float4*>(frow + 4)) : f4z;
    s[0]=fa.x; s[1]=fa.y; s[2]=fa.z; s[3]=fa.w;
    s[4]=fb.x; s[5]=fb.y; s[6]=fb.z; s[7]=fb.w;
    s[8]=fc.x; s[9]=fc.y; s[10]=fc.z; s[11]=fc.w;
}

__device__ __forceinline__ void tap_row(const float* __restrict__ ci, size_t cstride,
                                        const float s[12], float4& acc) {
#pragma unroll
    for (int j = 0; j < KK; j++) {
        const float4 cv =
            __ldcs(reinterpret_cast<const float4*>(ci + (size_t)j * cstride));
        acc.x = fmaf(cv.x, s[j + 2], acc.x);
        acc.y = fmaf(cv.y, s[j + 3], acc.y);
        acc.z = fmaf(cv.z, s[j + 4], acc.z);
        acc.w = fmaf(cv.w, s[j + 5], acc.w);
    }
}

__global__ __launch_bounds__(TX * 2, 12)
void kpn_conv_kernel(const float* __restrict__ frames,
                     const float* __restrict__ core,
                     float* __restrict__ out) {
    const int tile = blockIdx.x;    // H / TILE_H
    const int c    = blockIdx.y;    // channel
    const int b    = blockIdx.z;    // batch

    const size_t plane   = (size_t)HEI * WID;                 // 65536
    const float* fbase   = frames + ((size_t)b * CH + c) * plane;
    const float* cbase   = core   + ((size_t)b * 25 * CH + c) * plane;
    const size_t cstride = (size_t)CH * plane;                // tap stride

    const int w4 = threadIdx.x * 4;                           // first pixel col
    const int h  = tile * TILE_H + threadIdx.y * 2;           // first of 2 rows

    const float* crow = cbase + (size_t)h * WID + w4;

    float4 acc0 = make_float4(0.f, 0.f, 0.f, 0.f);            // row h
    float4 acc1 = acc0;                                        // row h+1

    float s[12];

    // ---- peeled r=0: frame row h-2 feeds only acc0 (tap i=0) ----
    frame_window(fbase, h - PAD, w4, s);
    tap_row(crow, cstride, s, acc0);

    // ---- main body r=1..4: frame row feeds acc0 (tap r) and acc1 (tap r-1) ----
#pragma unroll 1
    for (int r = 1; r < KK; r++) {
        frame_window(fbase, h - PAD + r, w4, s);
        tap_row(crow + (size_t)(r * KK) * cstride,             cstride, s, acc0);
        tap_row(crow + WID + (size_t)((r - 1) * KK) * cstride, cstride, s, acc1);
    }

    // ---- peeled r=5: frame row h+3 feeds only acc1 (tap i=4) ----
    frame_window(fbase, h - PAD + KK, w4, s);
    tap_row(crow + WID + (size_t)(4 * KK) * cstride, cstride, s, acc1);

    float* orow = out + ((size_t)b * CH + c) * plane + (size_t)h * WID + w4;
    __stcs(reinterpret_cast<float4*>(orow), acc0);
    __stcs(reinterpret_cast<float4*>(orow + WID), acc1);
}

extern "C" void kernel_launch(void* const* d_in, const int* in_sizes, int n_in,
                              void* d_out, int out_size) {
    const float* frames = (const float*)d_in[0];
    const float* core   = (const float*)d_in[1];
    // d_in[2] = rate (scalar, fixed 1 for this instance)
    float* out = (float*)d_out;

    dim3 block(TX, 2, 1);                   // 128 threads, 4 output rows per CTA
    dim3 grid(HEI / TILE_H, CH, 16);        // 64 x 3 x 16 = 3072 CTAs
    kpn_conv_kernel<<<grid, block>>>(frames, core, out);
}